// round 16
// baseline (speedup 1.0000x reference)
#include <cuda_runtime.h>
#include <cuda_bf16.h>
#include <math.h>
#include <stdint.h>

// Problem constants
#define BZ 4
#define NN 3136
#define CC 256
#define HH 8
#define HD 32
#define PL 196
#define IMH 56
#define IMW 56
#define KTAB 2048

// ---------------- scratch (device globals; no allocation allowed) -------------
__device__ float g_q   [BZ * NN * CC];
__device__ float g_kv  [BZ * NN * 512];
__device__ float g_xsr [BZ * NN * CC];
__device__ float g_tabT[HH * KTAB];          // transposed CPB table [h][t]
// bf16 hi/lo split buffers
__device__ __nv_bfloat16 g_xh  [BZ * NN * CC];
__device__ __nv_bfloat16 g_xl  [BZ * NN * CC];
__device__ __nv_bfloat16 g_xph [BZ * PL * CC];
__device__ __nv_bfloat16 g_xpL [BZ * PL * CC];
__device__ __nv_bfloat16 g_ath [BZ * NN * CC];
__device__ __nv_bfloat16 g_atl [BZ * NN * CC];
// prepared pooled K (smem-layout) and V^T, bf16 hi/lo
__device__ __align__(16) __nv_bfloat16 g_kph [BZ * HH * 224 * 40];
__device__ __align__(16) __nv_bfloat16 g_kpl [BZ * HH * 224 * 40];
__device__ __align__(16) __nv_bfloat16 g_vth [BZ * HH * 32 * 216];
__device__ __align__(16) __nv_bfloat16 g_vtl [BZ * HH * 32 * 216];

// ---------------- helpers ------------------------------------------------------
__device__ __forceinline__ uint32_t smem_u32(const void* p) {
    uint32_t a;
    asm("{ .reg .u64 t; cvta.to.shared.u64 t, %1; cvt.u32.u64 %0, t; }"
        : "=r"(a) : "l"(p));
    return a;
}
__device__ __forceinline__ void split4(float4 v, uint2& hi, uint2& lo) {
    float h0 = __bfloat162float(__float2bfloat16_rn(v.x));
    float h1 = __bfloat162float(__float2bfloat16_rn(v.y));
    float h2 = __bfloat162float(__float2bfloat16_rn(v.z));
    float h3 = __bfloat162float(__float2bfloat16_rn(v.w));
    __nv_bfloat162 ph0 = __floats2bfloat162_rn(h0, h1);
    __nv_bfloat162 ph1 = __floats2bfloat162_rn(h2, h3);
    __nv_bfloat162 pl0 = __floats2bfloat162_rn(v.x - h0, v.y - h1);
    __nv_bfloat162 pl1 = __floats2bfloat162_rn(v.z - h2, v.w - h3);
    hi.x = *(uint32_t*)&ph0; hi.y = *(uint32_t*)&ph1;
    lo.x = *(uint32_t*)&pl0; lo.y = *(uint32_t*)&pl1;
}
__device__ __forceinline__ void ldsm4(uint32_t* r, uint32_t addr) {
    asm volatile("ldmatrix.sync.aligned.m8n8.x4.shared.b16 {%0,%1,%2,%3}, [%4];"
                 : "=r"(r[0]), "=r"(r[1]), "=r"(r[2]), "=r"(r[3]) : "r"(addr));
}
__device__ __forceinline__ void mma_bf16(float* d, const uint32_t* a,
                                         uint32_t b0, uint32_t b1) {
    asm volatile(
        "mma.sync.aligned.m16n8k16.row.col.f32.bf16.bf16.f32 "
        "{%0,%1,%2,%3},{%4,%5,%6,%7},{%8,%9},{%0,%1,%2,%3};"
        : "+f"(d[0]), "+f"(d[1]), "+f"(d[2]), "+f"(d[3])
        : "r"(a[0]), "r"(a[1]), "r"(a[2]), "r"(a[3]), "r"(b0), "r"(b1));
}

// ---------------- split: fp32 -> bf16 hi/lo -----------------------------------
__global__ __launch_bounds__(256) void split_kernel(
    const float* __restrict__ src, __nv_bfloat16* __restrict__ hi,
    __nv_bfloat16* __restrict__ lo, int n4)
{
    int i = blockIdx.x * 256 + threadIdx.x;
    if (i >= n4) return;
    float4 v = ((const float4*)src)[i];
    uint2 h, l;
    split4(v, h, l);
    ((uint2*)hi)[i] = h;
    ((uint2*)lo)[i] = l;
}

// ---------------- bf16 3-pass GEMM mainloop (device) ---------------------------
#define A_H 0
#define A_L 16384
#define B_H 32768
#define B_L 65536
#define SMEM_GEMM 98304

__device__ __forceinline__ void gemm_mainloop(
    char* smem, const __nv_bfloat16* __restrict__ Ah,
    const __nv_bfloat16* __restrict__ Al, const float* __restrict__ W,
    int M, int m0, int n0, float acc[2][4][4])
{
    const uint32_t sb = smem_u32(smem);
    const int tid = threadIdx.x;
    const int lane = tid & 31, wid = tid >> 5;
    const int warpM = wid & 3, warpN = wid >> 2;

    #pragma unroll
    for (int it = 0; it < 16; it++) {
        int idx = tid + it * 256;
        int n = idx >> 6, c4 = idx & 63;
        float4 wv = *(const float4*)&W[(size_t)(n0 + n) * 256 + c4 * 4];
        uint2 hi, lo;
        split4(wv, hi, lo);
        uint32_t off = n * 512 + ((c4 >> 4) << 7) +
                       (((((c4 >> 1) & 7) ^ (n & 7))) << 4) + ((c4 & 1) << 3);
        *(uint2*)(smem + B_H + off) = hi;
        *(uint2*)(smem + B_L + off) = lo;
    }

    #pragma unroll
    for (int mt = 0; mt < 2; mt++)
        #pragma unroll
        for (int nt = 0; nt < 4; nt++)
            #pragma unroll
            for (int i = 0; i < 4; i++) acc[mt][nt][i] = 0.f;

    const uint4 z16 = make_uint4(0, 0, 0, 0);
    uint4 pah[4], pal[4];
    #pragma unroll
    for (int it = 0; it < 4; it++) {
        int idx = tid + it * 256;
        int row = idx >> 3, seg = idx & 7;
        int gr = m0 + row;
        pah[it] = (gr < M) ? *(const uint4*)&Ah[(size_t)gr * 256 + seg * 8] : z16;
        pal[it] = (gr < M) ? *(const uint4*)&Al[(size_t)gr * 256 + seg * 8] : z16;
    }

    const int a_row_in = ((lane >> 3) & 1) * 8 + (lane & 7);
    const int a_kseg   = (lane >> 4) & 1;
    const int b_row_in = ((lane >> 4) & 1) * 8 + (lane & 7);
    const int b_kseg   = (lane >> 3) & 1;

    for (int ch = 0; ch < 4; ch++) {
        __syncthreads();
        #pragma unroll
        for (int it = 0; it < 4; it++) {
            int idx = tid + it * 256;
            int row = idx >> 3, seg = idx & 7;
            uint32_t off = row * 128 + ((seg ^ (row & 7)) << 4);
            *(uint4*)(smem + A_H + off) = pah[it];
            *(uint4*)(smem + A_L + off) = pal[it];
        }
        __syncthreads();

        if (ch < 3) {
            #pragma unroll
            for (int it = 0; it < 4; it++) {
                int idx = tid + it * 256;
                int row = idx >> 3, seg = idx & 7;
                int gr = m0 + row;
                size_t gb = (size_t)gr * 256 + (ch + 1) * 64 + seg * 8;
                pah[it] = (gr < M) ? *(const uint4*)&Ah[gb] : z16;
                pal[it] = (gr < M) ? *(const uint4*)&Al[gb] : z16;
            }
        }

        #pragma unroll
        for (int s = 0; s < 4; s++) {
            uint32_t ah[2][4], al[2][4], bh[2][4], bl[2][4];
            #pragma unroll
            for (int mt = 0; mt < 2; mt++) {
                int r = warpM * 32 + mt * 16 + a_row_in;
                uint32_t off = r * 128 + (((s * 2 + a_kseg) ^ (r & 7)) << 4);
                ldsm4(ah[mt], sb + A_H + off);
                ldsm4(al[mt], sb + A_L + off);
            }
            #pragma unroll
            for (int np = 0; np < 2; np++) {
                int n = warpN * 32 + np * 16 + b_row_in;
                uint32_t off = n * 512 + ch * 128 +
                               (((s * 2 + b_kseg) ^ (n & 7)) << 4);
                ldsm4(bh[np], sb + B_H + off);
                ldsm4(bl[np], sb + B_L + off);
            }
            #pragma unroll
            for (int mt = 0; mt < 2; mt++)
                #pragma unroll
                for (int np = 0; np < 2; np++) {
                    float* dl = acc[mt][2 * np];
                    float* dh = acc[mt][2 * np + 1];
                    mma_bf16(dl, ah[mt], bh[np][0], bh[np][1]);
                    mma_bf16(dl, al[mt], bh[np][0], bh[np][1]);
                    mma_bf16(dl, ah[mt], bl[np][0], bl[np][1]);
                    mma_bf16(dh, ah[mt], bh[np][2], bh[np][3]);
                    mma_bf16(dh, al[mt], bh[np][2], bh[np][3]);
                    mma_bf16(dh, ah[mt], bl[np][2], bl[np][3]);
                }
        }
    }
}

// standard epilogue GEMM body
__device__ __forceinline__ void gemm_body(
    char* smem, const __nv_bfloat16* __restrict__ Ah,
    const __nv_bfloat16* __restrict__ Al, const float* __restrict__ W,
    const float* __restrict__ bias, float* __restrict__ C,
    int M, int N, int act, int m0, int n0)
{
    float acc[2][4][4];
    gemm_mainloop(smem, Ah, Al, W, M, m0, n0, acc);

    const int lane = threadIdx.x & 31, wid = threadIdx.x >> 5;
    const int gid = lane >> 2, tig = lane & 3;
    const int warpM = wid & 3, warpN = wid >> 2;

    const bool donorm = (act == 2) && (n0 + warpN * 32) < 256;
    #pragma unroll
    for (int mt = 0; mt < 2; mt++) {
        int r0 = m0 + warpM * 32 + mt * 16 + gid;
        int r1 = r0 + 8;
        float v0[4][2], v1[4][2];
        #pragma unroll
        for (int nt = 0; nt < 4; nt++) {
            int cb = n0 + warpN * 32 + nt * 8 + 2 * tig;
            float b0 = bias[cb], b1 = bias[cb + 1];
            v0[nt][0] = acc[mt][nt][0] + b0; v0[nt][1] = acc[mt][nt][1] + b1;
            v1[nt][0] = acc[mt][nt][2] + b0; v1[nt][1] = acc[mt][nt][3] + b1;
        }
        if (act == 1) {
            #pragma unroll
            for (int nt = 0; nt < 4; nt++)
                #pragma unroll
                for (int i = 0; i < 2; i++) {
                    v0[nt][i] = 0.5f * v0[nt][i] *
                                (1.f + erff(v0[nt][i] * 0.70710678118654752f));
                    v1[nt][i] = 0.5f * v1[nt][i] *
                                (1.f + erff(v1[nt][i] * 0.70710678118654752f));
                }
        } else if (donorm) {
            float ss0 = 0.f, ss1 = 0.f;
            #pragma unroll
            for (int nt = 0; nt < 4; nt++) {
                ss0 += v0[nt][0] * v0[nt][0] + v0[nt][1] * v0[nt][1];
                ss1 += v1[nt][0] * v1[nt][0] + v1[nt][1] * v1[nt][1];
            }
            ss0 += __shfl_xor_sync(0xffffffffu, ss0, 1);
            ss0 += __shfl_xor_sync(0xffffffffu, ss0, 2);
            ss1 += __shfl_xor_sync(0xffffffffu, ss1, 1);
            ss1 += __shfl_xor_sync(0xffffffffu, ss1, 2);
            float inv0 = 1.f / fmaxf(sqrtf(ss0), 1e-12f);
            float inv1 = 1.f / fmaxf(sqrtf(ss1), 1e-12f);
            #pragma unroll
            for (int nt = 0; nt < 4; nt++) {
                v0[nt][0] *= inv0; v0[nt][1] *= inv0;
                v1[nt][0] *= inv1; v1[nt][1] *= inv1;
            }
        }
        #pragma unroll
        for (int nt = 0; nt < 4; nt++) {
            int cb = n0 + warpN * 32 + nt * 8 + 2 * tig;
            if (r0 < M)
                *(float2*)&C[(size_t)r0 * N + cb] = make_float2(v0[nt][0], v0[nt][1]);
            if (r1 < M)
                *(float2*)&C[(size_t)r1 * N + cb] = make_float2(v1[nt][0], v1[nt][1]);
        }
    }
}

__global__ __launch_bounds__(256) void gemm_bf16(
    const __nv_bfloat16* __restrict__ Ah, const __nv_bfloat16* __restrict__ Al,
    const float* __restrict__ W, const float* __restrict__ bias,
    float* __restrict__ C, int M, int N, int act)
{
    extern __shared__ __align__(1024) char smem[];
    gemm_body(smem, Ah, Al, W, bias, C, M, N, act,
              blockIdx.y * 128, blockIdx.x * 64);
}

// fused q/kv/sr GEMM
__global__ __launch_bounds__(256) void gemm_qkvsr(
    const __nv_bfloat16* __restrict__ Ah, const __nv_bfloat16* __restrict__ Al,
    const float* __restrict__ q_w, const float* __restrict__ q_b,
    const float* __restrict__ kv_w, const float* __restrict__ kv_b,
    const float* __restrict__ sr_w, const float* __restrict__ sr_b,
    float* __restrict__ Cq, float* __restrict__ Ckv, float* __restrict__ Cxsr,
    int M)
{
    extern __shared__ __align__(1024) char smem[];
    const int bx = blockIdx.x;
    const float *W, *bias;
    float* C;
    int N, n0, act;
    if (bx < 4)       { W = q_w;  bias = q_b;  C = Cq;   N = 256; n0 = bx * 64;        act = 0; }
    else if (bx < 12) { W = kv_w; bias = kv_b; C = Ckv;  N = 512; n0 = (bx - 4) * 64;  act = 2; }
    else              { W = sr_w; bias = sr_b; C = Cxsr; N = 256; n0 = (bx - 12) * 64; act = 1; }
    gemm_body(smem, Ah, Al, W, bias, C, M, N, act, blockIdx.y * 128, n0);
}

// pooled-kv GEMM with fused prep
__global__ __launch_bounds__(256) void gemm_kvp_prep(
    const __nv_bfloat16* __restrict__ Ah, const __nv_bfloat16* __restrict__ Al,
    const float* __restrict__ kv_w, const float* __restrict__ kv_b,
    __nv_bfloat16* __restrict__ kph, __nv_bfloat16* __restrict__ kpl,
    __nv_bfloat16* __restrict__ vth, __nv_bfloat16* __restrict__ vtl,
    int M)
{
    extern __shared__ __align__(1024) char smem[];
    const int m0 = blockIdx.y * 128, n0 = blockIdx.x * 64;
    float acc[2][4][4];
    gemm_mainloop(smem, Ah, Al, kv_w, M, m0, n0, acc);

    const int lane = threadIdx.x & 31, wid = threadIdx.x >> 5;
    const int gid = lane >> 2, tig = lane & 3;
    const int warpM = wid & 3, warpN = wid >> 2;

    const int colbase = n0 + warpN * 32;
    const bool isK = colbase < 256;
    const int h = (colbase & 255) >> 5;

    #pragma unroll
    for (int mt = 0; mt < 2; mt++) {
        int r0 = m0 + warpM * 32 + mt * 16 + gid;
        int r1 = r0 + 8;
        float v0[4][2], v1[4][2];
        #pragma unroll
        for (int nt = 0; nt < 4; nt++) {
            int cb = colbase + nt * 8 + 2 * tig;
            float b0 = kv_b[cb], b1 = kv_b[cb + 1];
            v0[nt][0] = acc[mt][nt][0] + b0; v0[nt][1] = acc[mt][nt][1] + b1;
            v1[nt][0] = acc[mt][nt][2] + b0; v1[nt][1] = acc[mt][nt][3] + b1;
        }
        if (isK) {
            float ss0 = 0.f, ss1 = 0.f;
            #pragma unroll
            for (int nt = 0; nt < 4; nt++) {
                ss0 += v0[nt][0] * v0[nt][0] + v0[nt][1] * v0[nt][1];
                ss1 += v1[nt][0] * v1[nt][0] + v1[nt][1] * v1[nt][1];
            }
            ss0 += __shfl_xor_sync(0xffffffffu, ss0, 1);
            ss0 += __shfl_xor_sync(0xffffffffu, ss0, 2);
            ss1 += __shfl_xor_sync(0xffffffffu, ss1, 1);
            ss1 += __shfl_xor_sync(0xffffffffu, ss1, 2);
            float inv0 = 1.f / fmaxf(sqrtf(ss0), 1e-12f);
            float inv1 = 1.f / fmaxf(sqrtf(ss1), 1e-12f);
            #pragma unroll
            for (int nt = 0; nt < 4; nt++) {
                v0[nt][0] *= inv0; v0[nt][1] *= inv0;
                v1[nt][0] *= inv1; v1[nt][1] *= inv1;
            }
        }
        #pragma unroll
        for (int rsel = 0; rsel < 2; rsel++) {
            int r = rsel ? r1 : r0;
            if (r >= M) continue;
            int bb = r / PL, p = r - bb * PL;
            int bh = bb * HH + h;
            float (*vv)[2] = rsel ? v1 : v0;
            if (isK) {
                size_t base = (size_t)(bh * 224 + p) * 40;
                #pragma unroll
                for (int nt = 0; nt < 4; nt++) {
                    int d0 = nt * 8 + 2 * tig;
                    float a0 = vv[nt][0], a1 = vv[nt][1];
                    __nv_bfloat162 hb = __floats2bfloat162_rn(a0, a1);
                    float h0 = __bfloat162float(__low2bfloat16(hb));
                    float h1 = __bfloat162float(__high2bfloat16(hb));
                    __nv_bfloat162 lb = __floats2bfloat162_rn(a0 - h0, a1 - h1);
                    *(__nv_bfloat162*)&kph[base + d0] = hb;
                    *(__nv_bfloat162*)&kpl[base + d0] = lb;
                }
            } else {
                #pragma unroll
                for (int nt = 0; nt < 4; nt++)
                    #pragma unroll
                    for (int i = 0; i < 2; i++) {
                        int d = nt * 8 + 2 * tig + i;
                        float a = vv[nt][i];
                        __nv_bfloat16 hb = __float2bfloat16_rn(a);
                        size_t adr = (size_t)(bh * 32 + d) * 216 + p;
                        vth[adr] = hb;
                        vtl[adr] = __float2bfloat16_rn(a - __bfloat162float(hb));
                    }
            }
        }
    }
}

// ---------------- 4x4 average pool + layernorm (bf16 hi/lo out) ----------------
__global__ __launch_bounds__(256) void pool_ln_kernel(
    const float* __restrict__ xsr, const float* __restrict__ gam,
    const float* __restrict__ bet, __nv_bfloat16* __restrict__ xph,
    __nv_bfloat16* __restrict__ xpl)
{
    int bp = blockIdx.x;
    int b = bp / PL, p = bp % PL;
    int ph = p / 14, pw = p % 14;
    int c = threadIdx.x;

    float s = 0.f;
    #pragma unroll
    for (int i = 0; i < 4; i++)
        #pragma unroll
        for (int j = 0; j < 4; j++) {
            int n = (ph * 4 + i) * IMW + pw * 4 + j;
            s += xsr[((size_t)b * NN + n) * CC + c];
        }
    s *= (1.f / 16.f);

    __shared__ float r1[256], r2[256];
    r1[c] = s;
    r2[c] = s * s;
    __syncthreads();
    for (int st = 128; st > 0; st >>= 1) {
        if (c < st) { r1[c] += r1[c + st]; r2[c] += r2[c + st]; }
        __syncthreads();
    }
    float mean = r1[0] * (1.f / 256.f);
    float var  = r2[0] * (1.f / 256.f) - mean * mean;
    float invs = rsqrtf(var + 1e-5f);
    float val = (s - mean) * invs * gam[c] + bet[c];
    __nv_bfloat16 hb = __float2bfloat16_rn(val);
    xph[(size_t)bp * CC + c] = hb;
    xpl[(size_t)bp * CC + c] = __float2bfloat16_rn(val - __bfloat162float(hb));
}

// ---------------- CPB table: 4 t per block, transposed output ------------------
__global__ __launch_bounds__(256) void tab_kernel(
    const float* __restrict__ rct, const float* __restrict__ w1,
    const float* __restrict__ b1, const float* __restrict__ w2,
    const float* __restrict__ b2, float* __restrict__ tabT)
{
    __shared__ float sh[4 * 512];
    const int tid = threadIdx.x;
    const int t0 = blockIdx.x * 4;

    #pragma unroll
    for (int u = 0; u < 8; u++) {
        int idx = tid + u * 256;
        int tl = idx >> 9, j = idx & 511;
        int t = t0 + tl;
        sh[idx] = fmaxf(0.f, rct[t * 2] * w1[j * 2] + rct[t * 2 + 1] * w1[j * 2 + 1] + b1[j]);
    }
    __syncthreads();

    const int wid = tid >> 5, lane = tid & 31;  // warp = head
    float w2r[16];
    #pragma unroll
    for (int i = 0; i < 16; i++) w2r[i] = w2[wid * 512 + lane + i * 32];
    float bb = b2[wid];
    #pragma unroll
    for (int tl = 0; tl < 4; tl++) {
        float s = 0.f;
        #pragma unroll
        for (int i = 0; i < 16; i++) s += sh[tl * 512 + lane + i * 32] * w2r[i];
        #pragma unroll
        for (int o = 16; o > 0; o >>= 1) s += __shfl_xor_sync(0xffffffffu, s, o);
        if (lane == 0) tabT[wid * KTAB + t0 + tl] = s + bb;
    }
}

// ---------------- MMA attention (512 threads, warp-specialized) ----------------
#define SP_OFF   0        // logits fp32 [64][228]; later probs bf16 hi@0, lo@+464B
#define SKH_OFF  58368    // K_pool hi bf16 [224][40]
#define SKL_OFF  76288
#define SVTH_OFF 94208    // V^T hi bf16 [32][216]
#define SVTL_OFF 108032
#define SQH_OFF  121856   // q_scaled hi bf16 [64][40]
#define SQL_OFF  126976
#define SQS_OFF  132096   // q_scaled fp32 [64][33] (reused as output partial A)
#define SQN_OFF  140544   // q_norm fp32 [64][33]   (reused as output partial B)
#define SLOC_OFF 148992   // local weights [64][12]
#define SLOC2_OFF 152064  // raw local logits [64][12]
#define SLT_OFF  155136   // ltok head slice [32*9]
#define SRB_OFF  156288   // rpb[9] @0, lbias[9] @16
#define SKV_OFF  156416   // local K (then V) window [280][36] fp32
#define STAB_OFF 196736   // CPB column for this head [2048] fp32
#define SMEM_ATTN 204928

__global__ __launch_bounds__(512) void attn_mma(
    const float* __restrict__ q, const float* __restrict__ qe,
    const float* __restrict__ temp, const float* __restrict__ sls,
    const float* __restrict__ kv,
    const __nv_bfloat16* __restrict__ kph, const __nv_bfloat16* __restrict__ kpl,
    const __nv_bfloat16* __restrict__ vth, const __nv_bfloat16* __restrict__ vtl,
    const float* __restrict__ tabT, const int* __restrict__ rpi,
    const float* __restrict__ rpb, const float* __restrict__ ltok,
    const float* __restrict__ lbias,
    __nv_bfloat16* __restrict__ oh, __nv_bfloat16* __restrict__ ol)
{
    extern __shared__ __align__(1024) char smem[];
    const uint32_t sb = smem_u32(smem);
    float* sP    = (float*)(smem + SP_OFF);
    float* sQs   = (float*)(smem + SQS_OFF);
    float* sQn   = (float*)(smem + SQN_OFF);
    float* sLoc  = (float*)(smem + SLOC_OFF);
    float* sLoc2 = (float*)(smem + SLOC2_OFF);
    float* sLt   = (float*)(smem + SLT_OFF);
    float* sRb   = (float*)(smem + SRB_OFF);
    float* sKV   = (float*)(smem + SKV_OFF);
    float* sTab  = (float*)(smem + STAB_OFF);

    const int b = blockIdx.z, h = blockIdx.y;
    const int n0 = blockIdx.x * 64;
    const int tid = threadIdx.x, lane = tid & 31, wid = tid >> 5;
    const int gid = lane >> 2, tig = lane & 3;
    const int bh = b * HH + h;
    const int rstart = n0 / IMW - 1;

    // ---- staging: prepared K / V^T copies ----
    {
        const uint4* gkh = (const uint4*)(kph + (size_t)bh * 224 * 40);
        const uint4* gkl = (const uint4*)(kpl + (size_t)bh * 224 * 40);
        uint4* skh = (uint4*)(smem + SKH_OFF);
        uint4* skl = (uint4*)(smem + SKL_OFF);
        for (int i = tid; i < 1120; i += 512) { skh[i] = gkh[i]; skl[i] = gkl[i]; }
        const uint4* gvh = (const uint4*)(vth + (size_t)bh * 32 * 216);
        const uint4* gvl = (const uint4*)(vtl + (size_t)bh * 32 * 216);
        uint4* svh = (uint4*)(smem + SVTH_OFF);
        uint4* svl = (uint4*)(smem + SVTL_OFF);
        for (int i = tid; i < 864; i += 512) { svh[i] = gvh[i]; svl[i] = gvl[i]; }
        for (int i = tid; i < 288; i += 512) sLt[i] = ltok[h * 288 + i];
        if (tid < 9) sRb[tid] = rpb[h * 9 + tid];
        else if (tid >= 32 && tid < 41) sRb[16 + tid - 32] = lbias[h * 9 + tid - 32];
        for (int i = tid; i < KTAB; i += 512) sTab[i] = tabT[h * KTAB + i];
    }
    // zero pads: K rows 196..223, V^T cols 196..207
    {
        const uint4 z = make_uint4(0, 0, 0, 0);
        for (int i = tid; i < 112; i += 512) {
            int row = 196 + (i >> 2), seg = i & 3;
            *(uint4*)(smem + SKH_OFF + row * 80 + seg * 16) = z;
            *(uint4*)(smem + SKL_OFF + row * 80 + seg * 16) = z;
        }
        for (int i = tid; i < 192; i += 512) {
            int d = i / 6, k = i % 6;
            *(uint32_t*)(smem + SVTH_OFF + d * 432 + 392 + k * 4) = 0;
            *(uint32_t*)(smem + SVTL_OFF + d * 432 + 392 + k * 4) = 0;
        }
    }
    // ---- stage local K window: 5 image rows x 56 cols x 32 d, stride 36 ----
    for (int i = tid; i < 280 * 8; i += 512) {
        int pos = i >> 3, seg = i & 7;
        int rr2 = rstart + pos / IMW;
        float4 v = make_float4(0.f, 0.f, 0.f, 0.f);
        if (rr2 >= 0 && rr2 < IMH) {
            int nb = rr2 * IMW + pos % IMW;
            v = *(const float4*)&kv[((size_t)(b * NN + nb)) * 512 + h * HD + seg * 4];
        }
        *(float4*)&sKV[pos * 36 + seg * 4] = v;
    }
    // ---- stage q: norm + scale ----
    {
        float sp = log1pf(expf(temp[h]));
        float qev = qe[h * HD + lane];
        #pragma unroll
        for (int i = 0; i < 4; i++) {
            int row = wid * 4 + i;
            int n = n0 + row;
            float val = q[((size_t)(b * NN + n)) * CC + h * HD + lane];
            float ss = val * val;
            #pragma unroll
            for (int o = 16; o > 0; o >>= 1) ss += __shfl_xor_sync(0xffffffffu, ss, o);
            float inv = 1.f / fmaxf(sqrtf(ss), 1e-12f);
            float qnv = val * inv;
            float qsv = (qnv + qev) * sp * sls[n];
            sQs[row * 33 + lane] = qsv;
            sQn[row * 33 + lane] = qnv;
            __nv_bfloat16 hb = __float2bfloat16_rn(qsv);
            *(__nv_bfloat16*)(smem + SQH_OFF + row * 80 + lane * 2) = hb;
            *(__nv_bfloat16*)(smem + SQL_OFF + row * 80 + lane * 2) =
                __float2bfloat16_rn(qsv - __bfloat162float(hb));
        }
    }
    __syncthreads();

    const int a_row = ((lane >> 3) & 1) * 8 + (lane & 7);
    const int a_ks  = (lane >> 4) & 1;
    const int b_row = ((lane >> 4) & 1) * 8 + (lane & 7);
    const int b_ks  = (lane >> 3) & 1;

    // ---- phase 1 (warps 0-7): pooled logits = Qs @ K^T ----
    // ---- concurrently (warps 8-15): local logits + ltok dots, then V staging --
    if (wid < 8) {
        const int warpM = wid & 3, warpN = (wid >> 2) & 1;
        float acc[7][2][4];
        #pragma unroll
        for (int nt = 0; nt < 7; nt++)
            #pragma unroll
            for (int np = 0; np < 2; np++)
                #pragma unroll
                for (int i = 0; i < 4; i++) acc[nt][np][i] = 0.f;

        #pragma unroll
        for (int s = 0; s < 2; s++) {
            uint32_t ah[4], al[4];
            {
                int r = warpM * 16 + a_row;
                uint32_t off = SQH_OFF + r * 80 + (s * 2 + a_ks) * 16;
                ldsm4(ah, sb + off);
                ldsm4(al, sb + off + (SQL_OFF - SQH_OFF));
            }
            #pragma unroll
            for (int nt = 0; nt < 7; nt++) {
                int nr = warpN * 112 + nt * 16 + b_row;
                uint32_t off = SKH_OFF + nr * 80 + (s * 2 + b_ks) * 16;
                uint32_t bhf[4], blf[4];
                ldsm4(bhf, sb + off);
                ldsm4(blf, sb + off + (SKL_OFF - SKH_OFF));
                #pragma unroll
                for (int np = 0; np < 2; np++) {
                    float* d = acc[nt][np];
                    mma_bf16(d, ah, bhf[np * 2], bhf[np * 2 + 1]);
                    mma_bf16(d, al, bhf[np * 2], bhf[np * 2 + 1]);
                    mma_bf16(d, ah, blf[np * 2], blf[np * 2 + 1]);
                }
            }
        }
        int r0 = warpM * 16 + gid;
        #pragma unroll
        for (int nt = 0; nt < 7; nt++)
            #pragma unroll
            for (int np = 0; np < 2; np++) {
                int colb = warpN * 112 + nt * 16 + np * 8 + 2 * tig;
                *(float2*)&sP[r0 * 228 + colb] =
                    make_float2(acc[nt][np][0], acc[nt][np][1]);
                *(float2*)&sP[(r0 + 8) * 228 + colb] =
                    make_float2(acc[nt][np][2], acc[nt][np][3]);
            }
    } else {
        // local logits + learnable-token dots (K window from smem)
        for (int t5 = tid - 256; t5 < 64 * 9; t5 += 256) {
            int row = t5 / 9, l = t5 - row * 9;
            int n = n0 + row;
            int rr = n / IMW, cc2 = n % IMW;
            int r2 = rr + l / 3 - 1, c3 = cc2 + l % 3 - 1;
            float aloc = -3.4e38f;
            const float* Qs = &sQs[row * 33];
            if (r2 >= 0 && r2 < IMH && c3 >= 0 && c3 < IMW) {
                const float* kr = &sKV[((r2 - rstart) * IMW + c3) * 36];
                float s2 = 0.f;
                #pragma unroll
                for (int d4 = 0; d4 < 8; d4++) {
                    float4 t = *(const float4*)&kr[d4 * 4];
                    s2 += Qs[d4*4+0]*t.x + Qs[d4*4+1]*t.y + Qs[d4*4+2]*t.z + Qs[d4*4+3]*t.w;
                }
                aloc = s2 + sRb[l];
            }
            sLoc2[row * 12 + l] = aloc;
            const float* Qn = &sQn[row * 33];
            float t2 = 0.f;
            #pragma unroll
            for (int d = 0; d < 32; d++) t2 += Qn[d] * sLt[d * 9 + l];
            sLoc[row * 12 + l] = t2 + sRb[16 + l];
        }
        // barrier among warps 8-15 only, then overwrite K window with V window
        asm volatile("bar.sync 1, 256;" ::: "memory");
        for (int i = tid - 256; i < 280 * 8; i += 256) {
            int pos = i >> 3, seg = i & 7;
            int rr2 = rstart + pos / IMW;
            float4 v = make_float4(0.f, 0.f, 0.f, 0.f);
            if (rr2 >= 0 && rr2 < IMH) {
                int nb = rr2 * IMW + pos % IMW;
                v = *(const float4*)&kv[((size_t)(b * NN + nb)) * 512 + 256 + h * HD + seg * 4];
            }
            *(float4*)&sKV[pos * 36 + seg * 4] = v;
        }
    }
    __syncthreads();

    // ---- phase 1.5a: CPB bias gather from smem (all 512) ----
    #pragma unroll 4
    for (int i = tid; i < 64 * PL; i += 512) {
        int row = i / PL;
        int j = i - row * PL;
        sP[row * 228 + j] += sTab[rpi[(size_t)(n0 + row) * PL + j]];
    }
    __syncthreads();

    // ---- phase 2: softmax per row (16 warps x 4 rows) ----
    #pragma unroll
    for (int i = 0; i < 4; i++) {
        int row = wid * 4 + i;
        float* Pr = &sP[row * 228];

        float e[7];
        float mx = -3.4e38f;
        #pragma unroll
        for (int t = 0; t < 7; t++) {
            int j = lane + 32 * t;
            if (j < PL) { e[t] = Pr[j]; mx = fmaxf(mx, e[t]); }
            else e[t] = -3.4e38f;
        }
        float aloc = (lane < 9) ? sLoc2[row * 12 + lane] : -3.4e38f;
        mx = fmaxf(mx, aloc);
        #pragma unroll
        for (int o = 16; o > 0; o >>= 1)
            mx = fmaxf(mx, __shfl_xor_sync(0xffffffffu, mx, o));

        float sum = 0.f;
        #pragma unroll
        for (int t = 0; t < 7; t++) {
            int j = lane + 32 * t;
            if (j < PL) { e[t] = __expf(e[t] - mx); sum += e[t]; }
        }
        float el = 0.f;
        if (lane < 9) { el = __expf(aloc - mx); sum += el; }
        #pragma unroll
        for (int o = 16; o > 0; o >>= 1) sum += __shfl_xor_sync(0xffffffffu, sum, o);
        float inv = 1.f / sum;

        __nv_bfloat16* Ph = (__nv_bfloat16*)Pr;
        __nv_bfloat16* Pl2 = Ph + 232;
        #pragma unroll
        for (int t = 0; t < 7; t++) {
            int j = lane + 32 * t;
            if (j < PL) {
                float p = e[t] * inv;
                __nv_bfloat16 hb = __float2bfloat16_rn(p);
                Ph[j] = hb;
                Pl2[j] = __float2bfloat16_rn(p - __bfloat162float(hb));
            }
        }
        if (lane < 12) {
            Ph[PL + lane] = __float2bfloat16(0.f);
            Pl2[PL + lane] = __float2bfloat16(0.f);
        }
        if (lane < 9) sLoc[row * 12 + lane] += el * inv;
    }
    __syncthreads();

    // ---- phase 3: pooled output = P @ V, k-split across all 16 warps ----
    {
        const int ks = wid >> 3;            // 0: kt 0-6, 1: kt 7-12
        const int w8 = wid & 7;
        const int warpM = w8 & 3, warpN = (w8 >> 2) & 1;
        float acc[2][4];
        #pragma unroll
        for (int np = 0; np < 2; np++)
            #pragma unroll
            for (int i = 0; i < 4; i++) acc[np][i] = 0.f;

        const int nkt = ks ? 6 : 7;
        const int kbase = ks ? 7 : 0;
        #pragma unroll 7
        for (int k2 = 0; k2 < nkt; k2++) {
            int kt = kbase + k2;
            uint32_t ah[4], al[4], bhf[4], blf[4];
            int r = warpM * 16 + a_row;
            uint32_t offA = SP_OFF + r * 912 + (kt * 2 + a_ks) * 16;
            ldsm4(ah, sb + offA);
            ldsm4(al, sb + offA + 464);
            int nr = warpN * 16 + b_row;
            uint32_t offB = SVTH_OFF + nr * 432 + (kt * 2 + b_ks) * 16;
            ldsm4(bhf, sb + offB);
            ldsm4(blf, sb + offB + (SVTL_OFF - SVTH_OFF));
            #pragma unroll
            for (int np = 0; np < 2; np++) {
                float* d = acc[np];
                mma_bf16(d, ah, bhf[np * 2], bhf[np * 2 + 1]);
                mma_bf16(d, al, bhf[np * 2], bhf[np * 2 + 1]);
                mma_bf16(d, ah, blf[np * 2], blf[np * 2 + 1]);
            }
        }
        float* sO = ks ? sQn : sQs;   // partial buffers (q fp32 no longer needed)
        int r0 = warpM * 16 + gid;
        #pragma unroll
        for (int np = 0; np < 2; np++) {
            int colb = warpN * 16 + np * 8 + 2 * tig;
            sO[r0 * 33 + colb]         = acc[np][0];
            sO[r0 * 33 + colb + 1]     = acc[np][1];
            sO[(r0+8) * 33 + colb]     = acc[np][2];
            sO[(r0+8) * 33 + colb + 1] = acc[np][3];
        }
    }
    __syncthreads();

    // ---- phase 4: combine partials + local-V (from smem), split hi/lo, store --
    #pragma unroll
    for (int i = 0; i < 4; i++) {
        int row = wid * 4 + i;
        int n = n0 + row;
        int rr = n / IMW, cc2 = n % IMW;
        float o = sQs[row * 33 + lane] + sQn[row * 33 + lane];
        #pragma unroll
        for (int l = 0; l < 9; l++) {
            int r2 = rr + l / 3 - 1, c3 = cc2 + l % 3 - 1;
            if (r2 >= 0 && r2 < IMH && c3 >= 0 && c3 < IMW) {
                o += sLoc[row * 12 + l] *
                     sKV[((r2 - rstart) * IMW + c3) * 36 + lane];
            }
        }
        size_t oi = ((size_t)(b * NN) + n) * CC + h * HD + lane;
        __nv_bfloat16 hb = __float2bfloat16_rn(o);
        oh[oi] = hb;
        ol[oi] = __float2bfloat16_rn(o - __bfloat162float(hb));
    }
}

// -----------------------------------------------------------------------------
extern "C" void kernel_launch(void* const* d_in, const int* in_sizes, int n_in,
                              void* d_out, int out_size)
{
    const float* x      = (const float*)d_in[0];
    const int*   rpi    = (const int*)  d_in[3];
    const float* rct    = (const float*)d_in[4];
    const float* sls    = (const float*)d_in[5];
    const float* q_w    = (const float*)d_in[7];
    const float* q_b    = (const float*)d_in[8];
    const float* kv_w   = (const float*)d_in[9];
    const float* kv_b   = (const float*)d_in[10];
    const float* sr_w   = (const float*)d_in[11];
    const float* sr_b   = (const float*)d_in[12];
    const float* norm_g = (const float*)d_in[13];
    const float* norm_b = (const float*)d_in[14];
    const float* cpb1_w = (const float*)d_in[15];
    const float* cpb1_b = (const float*)d_in[16];
    const float* cpb2_w = (const float*)d_in[17];
    const float* cpb2_b = (const float*)d_in[18];
    const float* temp   = (const float*)d_in[19];
    const float* qe     = (const float*)d_in[20];
    const float* rpb    = (const float*)d_in[21];
    const float* ltok   = (const float*)d_in[22];
    const float* lbias  = (const float*)d_in[23];
    const float* proj_w = (const float*)d_in[24];
    const float* proj_b = (const float*)d_in[25];
    float* out = (float*)d_out;

    float *p_q, *p_kv, *p_xsr, *p_tabT;
    __nv_bfloat16 *p_xh, *p_xl, *p_xph, *p_xpL, *p_ath, *p_atl;
    __nv_bfloat16 *p_kph, *p_kpl, *p_vth, *p_vtl;
    cudaGetSymbolAddress((void**)&p_q,    g_q);
    cudaGetSymbolAddress((void**)&p_kv,   g_kv);
    cudaGetSymbolAddress((void**)&p_xsr,  g_xsr);
    cudaGetSymbolAddress((void**)&p_tabT, g_tabT);
    cudaGetSymbolAddress((void**)&p_xh,   g_xh);
    cudaGetSymbolAddress((void**)&p_xl,   g_xl);
    cudaGetSymbolAddress((void**)&p_xph,  g_xph);
    cudaGetSymbolAddress((void**)&p_xpL,  g_xpL);
    cudaGetSymbolAddress((void**)&p_ath,  g_ath);
    cudaGetSymbolAddress((void**)&p_atl,  g_atl);
    cudaGetSymbolAddress((void**)&p_kph,  g_kph);
    cudaGetSymbolAddress((void**)&p_kpl,  g_kpl);
    cudaGetSymbolAddress((void**)&p_vth,  g_vth);
    cudaGetSymbolAddress((void**)&p_vtl,  g_vtl);

    const int M = BZ * NN;  // 12544
    const int MP = BZ * PL; // 784

    cudaFuncSetAttribute(gemm_bf16, cudaFuncAttributeMaxDynamicSharedMemorySize, SMEM_GEMM);
    cudaFuncSetAttribute(gemm_qkvsr, cudaFuncAttributeMaxDynamicSharedMemorySize, SMEM_GEMM);
    cudaFuncSetAttribute(gemm_kvp_prep, cudaFuncAttributeMaxDynamicSharedMemorySize, SMEM_GEMM);
    cudaFuncSetAttribute(attn_mma, cudaFuncAttributeMaxDynamicSharedMemorySize, SMEM_ATTN);

    // 0: split x -> bf16 hi/lo
    split_kernel<<<(M * CC / 4 + 255) / 256, 256>>>(x, p_xh, p_xl, M * CC / 4);
    // 1: fused q + kv + sr GEMMs
    gemm_qkvsr<<<dim3(16, 98), 256, SMEM_GEMM>>>(
        p_xh, p_xl, q_w, q_b, kv_w, kv_b, sr_w, sr_b, p_q, p_kv, p_xsr, M);
    // 2: pool + layernorm (bf16 hi/lo out)
    pool_ln_kernel<<<BZ * PL, 256>>>(p_xsr, norm_g, norm_b, p_xph, p_xpL);
    // 3: CPB bias table (transposed out)
    tab_kernel<<<KTAB / 4, 256>>>(rct, cpb1_w, cpb1_b, cpb2_w, cpb2_b, p_tabT);
    // 4: pooled-kv GEMM with fused K/V^T bf16 prep
    gemm_kvp_prep<<<dim3(8, 7), 256, SMEM_GEMM>>>(
        p_xph, p_xpL, kv_w, kv_b, p_kph, p_kpl, p_vth, p_vtl, MP);
    // 5: MMA attention
    attn_mma<<<dim3(NN / 64, HH, BZ), 512, SMEM_ATTN>>>(
        p_q, qe, temp, sls, p_kv, p_kph, p_kpl, p_vth, p_vtl,
        p_tabT, rpi, rpb, ltok, lbias, p_ath, p_atl);
    // 6: output projection
    gemm_bf16<<<dim3(4, 98), 256, SMEM_GEMM>>>(p_ath, p_atl, proj_w, proj_b, out, M, 256, 0);
}